// round 1
// baseline (speedup 1.0000x reference)
#include <cuda_runtime.h>
#include <cuda_bf16.h>

// Problem: ann2_snn1 — sigmoid -> dual-exp IIR (feature-uniform coeffs) -> W proj -> LIF spikes
// Shapes: inputs [64, 500, 1024] f32; a1,a2 [500]; W [10,500]; b [10]; out [64,10,1024] f32
//
// Restructuring: a1/a2 are uniform across features, so IIR commutes with the
// linear projection:  W @ IIR(sig(x)) == IIR(W @ sig(x)).  Kernel 1 does the
// time-parallel projection (the 131 MB read + 328M FMAs); kernel 2 runs the
// tiny 640-channel serial IIR+LIF.

#define B_ 64
#define F_ 500
#define T_ 1024
#define O_ 10
#define CH (B_ * O_)   // 640 channels

// scratch: u[t][b*10+o]  (2.62 MB, fits L2)
__device__ float g_u[(size_t)T_ * CH];

// ---------------------------------------------------------------------------
// Kernel 1: u[t, b, o] = sum_f W[o,f] * sigmoid(inputs[b, f, t])
// grid = (T/128, B), block = 128 threads (one t per thread)
// ---------------------------------------------------------------------------
__global__ void __launch_bounds__(128) proj_kernel(const float* __restrict__ in,
                                                   const float* __restrict__ W) {
    // W staged in smem, padded to 12 floats per feature row -> 3x float4 loads
    __shared__ float Wsh[F_ * 12];   // 24 KB

    const int tid = threadIdx.x;
    const int b   = blockIdx.y;
    const int t   = blockIdx.x * 128 + tid;

    for (int i = tid; i < F_ * 12; i += 128) {
        int f = i / 12;
        int o = i - f * 12;
        Wsh[i] = (o < O_) ? W[o * F_ + f] : 0.0f;
    }
    __syncthreads();

    const float* row = in + (size_t)b * (F_ * T_) + t;   // stride T_ per feature
    const float4* W4 = (const float4*)Wsh;

    float acc0 = 0.f, acc1 = 0.f, acc2 = 0.f, acc3 = 0.f, acc4 = 0.f;
    float acc5 = 0.f, acc6 = 0.f, acc7 = 0.f, acc8 = 0.f, acc9 = 0.f;

#pragma unroll 4
    for (int f = 0; f < F_; f++) {
        float x = __ldg(row + (size_t)f * T_);
        // sigmoid: 1/(1+exp(-x)) via fast ex2 + fast reciprocal (~5e-7 rel err)
        float e = __expf(-x);
        float s = __fdividef(1.0f, 1.0f + e);

        float4 w0 = W4[f * 3 + 0];
        float4 w1 = W4[f * 3 + 1];
        float4 w2 = W4[f * 3 + 2];

        acc0 += w0.x * s;  acc1 += w0.y * s;  acc2 += w0.z * s;  acc3 += w0.w * s;
        acc4 += w1.x * s;  acc5 += w1.y * s;  acc6 += w1.z * s;  acc7 += w1.w * s;
        acc8 += w2.x * s;  acc9 += w2.y * s;
    }

    float* up = g_u + (size_t)t * CH + b * O_;
    up[0] = acc0;  up[1] = acc1;  up[2] = acc2;  up[3] = acc3;  up[4] = acc4;
    up[5] = acc5;  up[6] = acc6;  up[7] = acc7;  up[8] = acc8;  up[9] = acc9;
}

// ---------------------------------------------------------------------------
// Kernel 2: per-channel serial IIR + LIF over T.
//   y[t]  = a1*y[t-1] + a2*y[t-2] + u[t]
//   psc   = y[t] + b[o]
//   v     = dm * v * (1 - s_prev) + psc      (reset-on-spike)
//   s     = (v > 1)
// 640 channels, one thread each. Loads of u are warp-coalesced (stride CH in t).
// ---------------------------------------------------------------------------
__global__ void __launch_bounds__(128) iir_lif_kernel(const float* __restrict__ a1p,
                                                      const float* __restrict__ a2p,
                                                      const float* __restrict__ bias,
                                                      float* __restrict__ out) {
    const int ch = blockIdx.x * 128 + threadIdx.x;
    if (ch >= CH) return;
    const int b = ch / O_;
    const int o = ch - b * O_;

    const float a1 = __ldg(a1p);        // coefficients are feature-uniform
    const float a2 = __ldg(a2p);
    const float bo = __ldg(bias + o);
    const float dm = 0.7788007830714049f;   // exp(-1/TAU_M), TAU_M = 4

    float y1 = 0.f, y2 = 0.f, v = 0.f, s = 0.f;

    const float* up   = g_u + ch;
    float*       orow = out + (size_t)b * (O_ * T_) + (size_t)o * T_;

#pragma unroll 8
    for (int t = 0; t < T_; t++) {
        float x = up[(size_t)t * CH];
        // IIR (keep mul/add separate; avoid fma contraction vs reference)
        float y = __fadd_rn(__fadd_rn(__fmul_rn(a1, y1), __fmul_rn(a2, y2)), x);
        y2 = y1;
        y1 = y;
        float psc = __fadd_rn(y, bo);
        // LIF with reset-on-spike
        float vd = (s > 0.f) ? 0.f : v;
        v = __fadd_rn(__fmul_rn(dm, vd), psc);
        s = (v > 1.0f) ? 1.0f : 0.0f;
        orow[t] = s;
    }
}

// ---------------------------------------------------------------------------
extern "C" void kernel_launch(void* const* d_in, const int* in_sizes, int n_in,
                              void* d_out, int out_size) {
    (void)in_sizes; (void)n_in; (void)out_size;
    const float* inputs = (const float*)d_in[0];   // [64, 500, 1024]
    const float* a1     = (const float*)d_in[1];   // [500]
    const float* a2     = (const float*)d_in[2];   // [500]
    const float* W      = (const float*)d_in[3];   // [10, 500]
    const float* bias   = (const float*)d_in[4];   // [10]
    float*       out    = (float*)d_out;           // [64, 10, 1024]

    dim3 g1(T_ / 128, B_);
    proj_kernel<<<g1, 128>>>(inputs, W);

    iir_lif_kernel<<<(CH + 127) / 128, 128>>>(a1, a2, bias, out);
}

// round 7
// speedup vs baseline: 4.4070x; 4.4070x over previous
#include <cuda_runtime.h>
#include <cuda_bf16.h>

// ann2_snn1: sigmoid -> feature-uniform dual-exp IIR -> W proj (500->10) -> LIF spikes
// inputs [64,500,1024] f32; a1,a2 [500]; W [10,500]; b [10]; out [64,10,1024] f32
//
// IIR coeffs are feature-uniform, so IIR commutes with the linear projection:
//   W @ IIR(sig(x)) == IIR(W @ sig(x))
// Kernel 1: time-parallel projection (131 MB read, 328M FMA).
// Kernel 2: 640-channel serial IIR+LIF, double-buffered register tiles so the
//           L2 loads pipeline instead of serializing against the stores
//           (R1 failure mode: 490us with MLP=1 exposed load latency).

#define B_ 64
#define F_ 500
#define T_ 1024
#define O_ 10
#define CH (B_ * O_)   // 640 channels

// scratch: u[t][b*10+o]  (2.62 MB, L2-resident)
__device__ float g_u[(size_t)T_ * CH];

// ---------------------------------------------------------------------------
// Kernel 1: u[t, b, o] = sum_f W[o,f] * sigmoid(inputs[b, f, t])
// grid = (T/128, B), block = 128 (one t per thread)
// ---------------------------------------------------------------------------
__global__ void __launch_bounds__(128) proj_kernel(const float* __restrict__ in,
                                                   const float* __restrict__ W) {
    __shared__ float Wsh[F_ * 12];   // padded to 12 floats/row -> 3x float4

    const int tid = threadIdx.x;
    const int b   = blockIdx.y;
    const int t   = blockIdx.x * 128 + tid;

    for (int i = tid; i < F_ * 12; i += 128) {
        int f = i / 12;
        int o = i - f * 12;
        Wsh[i] = (o < O_) ? W[o * F_ + f] : 0.0f;
    }
    __syncthreads();

    const float* row = in + (size_t)b * (F_ * T_) + t;
    const float4* W4 = (const float4*)Wsh;

    float acc0 = 0.f, acc1 = 0.f, acc2 = 0.f, acc3 = 0.f, acc4 = 0.f;
    float acc5 = 0.f, acc6 = 0.f, acc7 = 0.f, acc8 = 0.f, acc9 = 0.f;

    // unroll 8: keep 8 independent LDGs in flight per warp so DRAM latency is
    // hidden even at ~3.5 blocks/SM (unroll 4 left only ~512B/warp in flight)
#pragma unroll 8
    for (int f = 0; f < F_; f++) {
        float x = __ldg(row + (size_t)f * T_);
        float e = __expf(-x);
        float s = __fdividef(1.0f, 1.0f + e);

        float4 w0 = W4[f * 3 + 0];
        float4 w1 = W4[f * 3 + 1];
        float4 w2 = W4[f * 3 + 2];

        acc0 += w0.x * s;  acc1 += w0.y * s;  acc2 += w0.z * s;  acc3 += w0.w * s;
        acc4 += w1.x * s;  acc5 += w1.y * s;  acc6 += w1.z * s;  acc7 += w1.w * s;
        acc8 += w2.x * s;  acc9 += w2.y * s;
    }

    float* up = g_u + (size_t)t * CH + b * O_;
    up[0] = acc0;  up[1] = acc1;  up[2] = acc2;  up[3] = acc3;  up[4] = acc4;
    up[5] = acc5;  up[6] = acc6;  up[7] = acc7;  up[8] = acc8;  up[9] = acc9;
}

// ---------------------------------------------------------------------------
// Kernel 2: per-channel serial IIR + LIF over T, register-tiled.
//   y[t] = a1*y[t-1] + a2*y[t-2] + u[t];  psc = y + b[o]
//   v    = fired ? psc : (dm*v + psc);    fired = v > 1;  s = fired
// block = 32 (1 warp), grid = 20 -> 20 SMs. TILE=16 double-buffered loads.
// ---------------------------------------------------------------------------
#define TILE_ 16

__global__ void __launch_bounds__(32) iir_lif_kernel(const float* __restrict__ a1p,
                                                     const float* __restrict__ a2p,
                                                     const float* __restrict__ bias,
                                                     float* __restrict__ out) {
    const int ch = blockIdx.x * 32 + threadIdx.x;
    if (ch >= CH) return;
    const int b = ch / O_;
    const int o = ch - b * O_;

    const float a1 = __ldg(a1p);   // feature-uniform
    const float a2 = __ldg(a2p);
    const float bo = __ldg(bias + o);
    const float dm = 0.7788007830714049f;   // exp(-1/4)

    float y1 = 0.f, y2 = 0.f, v = 0.f;
    bool fired = false;

    const float* up   = g_u + ch;
    float*       orow = out + (size_t)b * (O_ * T_) + (size_t)o * T_;

    float xa[TILE_], xb[TILE_];

    // prefetch tile 0 — 16 independent LDGs in flight
#pragma unroll
    for (int i = 0; i < TILE_; i++) xa[i] = __ldg(up + (size_t)i * CH);

    for (int t0 = 0; t0 < T_; t0 += TILE_) {
        // prefetch next tile while the serial chain below runs
        if (t0 + TILE_ < T_) {
#pragma unroll
            for (int i = 0; i < TILE_; i++)
                xb[i] = __ldg(up + (size_t)(t0 + TILE_ + i) * CH);
        }

        float sbuf[TILE_];
#pragma unroll
        for (int i = 0; i < TILE_; i++) {
            // IIR: exact rounding order of the reference (mul, mul, add, add)
            float y = __fadd_rn(__fadd_rn(__fmul_rn(a1, y1), __fmul_rn(a2, y2)), xa[i]);
            y2 = y1;
            y1 = y;
            float psc = __fadd_rn(y, bo);
            // leak path computed in parallel with the fired-predicate
            float vleak = __fadd_rn(__fmul_rn(dm, v), psc);
            v = fired ? psc : vleak;
            fired = (v > 1.0f);
            sbuf[i] = fired ? 1.0f : 0.0f;
        }

        // vectorized stores, off the critical path
        float4* o4 = (float4*)(orow + t0);
#pragma unroll
        for (int i = 0; i < TILE_ / 4; i++)
            o4[i] = make_float4(sbuf[4*i], sbuf[4*i+1], sbuf[4*i+2], sbuf[4*i+3]);

        // rotate buffers
#pragma unroll
        for (int i = 0; i < TILE_; i++) xa[i] = xb[i];
    }
}

// ---------------------------------------------------------------------------
extern "C" void kernel_launch(void* const* d_in, const int* in_sizes, int n_in,
                              void* d_out, int out_size) {
    (void)in_sizes; (void)n_in; (void)out_size;
    const float* inputs = (const float*)d_in[0];   // [64, 500, 1024]
    const float* a1     = (const float*)d_in[1];   // [500]
    const float* a2     = (const float*)d_in[2];   // [500]
    const float* W      = (const float*)d_in[3];   // [10, 500]
    const float* bias   = (const float*)d_in[4];   // [10]
    float*       out    = (float*)d_out;           // [64, 10, 1024]

    dim3 g1(T_ / 128, B_);
    proj_kernel<<<g1, 128>>>(inputs, W);

    iir_lif_kernel<<<CH / 32, 32>>>(a1, a2, bias, out);
}

// round 10
// speedup vs baseline: 4.8324x; 1.0965x over previous
#include <cuda_runtime.h>
#include <cuda_bf16.h>

// ann2_snn1: sigmoid -> feature-uniform dual-exp IIR -> W proj (500->10) -> LIF spikes
// inputs [64,500,1024] f32; a1,a2 [500]; W [10,500]; b [10]; out [64,10,1024] f32
//
// IIR coeffs are feature-uniform, so IIR commutes with the linear projection:
//   W @ IIR(sig(x)) == IIR(W @ sig(x))
// Kernel 1: time-parallel projection (131 MB read, 328M FMA).  [unchanged from R7]
// Kernel 2: 640-channel serial IIR+LIF. R7 measured 44.4us at 78 cyc/step:
//   per-tile L2 prefetch latency (~240cyc) + 32-MOV rotate exposed at every
//   16-step tile boundary. Fix: stage the block's whole 128KB u-slice in smem
//   first (coalesced, ~1us), then the serial chain reads 29-cyc LDS - no
//   double buffering needed, exposure ~2 cyc/step.

#define B_ 64
#define F_ 500
#define T_ 1024
#define O_ 10
#define CH (B_ * O_)   // 640 channels

// scratch: u[t][b*10+o]  (2.62 MB, L2-resident)
__device__ float g_u[(size_t)T_ * CH];

// ---------------------------------------------------------------------------
// Kernel 1: u[t, b, o] = sum_f W[o,f] * sigmoid(inputs[b, f, t])
// grid = (T/128, B), block = 128 (one t per thread)   [unchanged]
// ---------------------------------------------------------------------------
__global__ void __launch_bounds__(128) proj_kernel(const float* __restrict__ in,
                                                   const float* __restrict__ W) {
    __shared__ float Wsh[F_ * 12];   // padded to 12 floats/row -> 3x float4

    const int tid = threadIdx.x;
    const int b   = blockIdx.y;
    const int t   = blockIdx.x * 128 + tid;

    for (int i = tid; i < F_ * 12; i += 128) {
        int f = i / 12;
        int o = i - f * 12;
        Wsh[i] = (o < O_) ? W[o * F_ + f] : 0.0f;
    }
    __syncthreads();

    const float* row = in + (size_t)b * (F_ * T_) + t;
    const float4* W4 = (const float4*)Wsh;

    float acc0 = 0.f, acc1 = 0.f, acc2 = 0.f, acc3 = 0.f, acc4 = 0.f;
    float acc5 = 0.f, acc6 = 0.f, acc7 = 0.f, acc8 = 0.f, acc9 = 0.f;

#pragma unroll 8
    for (int f = 0; f < F_; f++) {
        float x = __ldg(row + (size_t)f * T_);
        float e = __expf(-x);
        float s = __fdividef(1.0f, 1.0f + e);

        float4 w0 = W4[f * 3 + 0];
        float4 w1 = W4[f * 3 + 1];
        float4 w2 = W4[f * 3 + 2];

        acc0 += w0.x * s;  acc1 += w0.y * s;  acc2 += w0.z * s;  acc3 += w0.w * s;
        acc4 += w1.x * s;  acc5 += w1.y * s;  acc6 += w1.z * s;  acc7 += w1.w * s;
        acc8 += w2.x * s;  acc9 += w2.y * s;
    }

    float* up = g_u + (size_t)t * CH + b * O_;
    up[0] = acc0;  up[1] = acc1;  up[2] = acc2;  up[3] = acc3;  up[4] = acc4;
    up[5] = acc5;  up[6] = acc6;  up[7] = acc7;  up[8] = acc8;  up[9] = acc9;
}

// ---------------------------------------------------------------------------
// Kernel 2: smem-staged serial IIR + LIF.
// grid = 20 blocks x 128 threads. Block owns 32 channels.
// Phase 1: all 4 warps stage u[0..1023][ch0..ch0+31] (128 KB) into smem.
// Phase 2: warp 0 runs the 1024-step serial chain from 29-cyc LDS.
// ---------------------------------------------------------------------------
#define TILE_ 16
#define SMEM_BYTES (T_ * 32 * sizeof(float))   // 131072

__global__ void __launch_bounds__(128) iir_lif_kernel(const float* __restrict__ a1p,
                                                      const float* __restrict__ a2p,
                                                      const float* __restrict__ bias,
                                                      float* __restrict__ out) {
    extern __shared__ float sm[];   // sm[t*32 + lane]

    const int tid = threadIdx.x;
    const int ch0 = blockIdx.x * 32;

    // Phase 1: coalesced stage-in. 8 float4 per t-row; i covers T_*8 = 8192 vecs.
    {
        float4* dst = (float4*)sm;
        for (int i = tid; i < T_ * 8; i += 128) {
            int t = i >> 3;
            int j = i & 7;
            dst[i] = *(const float4*)(g_u + (size_t)t * CH + ch0 + j * 4);
        }
    }
    __syncthreads();
    if (tid >= 32) return;          // warps 1-3 done (no further barriers)

    const int ch = ch0 + tid;
    const int b  = ch / O_;
    const int o  = ch - b * O_;

    const float a1 = __ldg(a1p);    // feature-uniform
    const float a2 = __ldg(a2p);
    const float bo = __ldg(bias + o);
    const float dm = 0.7788007830714049f;   // exp(-1/4)

    float y1 = 0.f, y2 = 0.f, v = 0.f;
    bool fired = false;

    float* orow = out + (size_t)b * (O_ * T_) + (size_t)o * T_;
    const float* mysm = sm + tid;   // stride 32 floats per t, conflict-free

    for (int t0 = 0; t0 < T_; t0 += TILE_) {
        // pull 16 steps from smem (29-cyc LDS, batched; independent of chain)
        float xt[TILE_];
#pragma unroll
        for (int i = 0; i < TILE_; i++) xt[i] = mysm[(t0 + i) * 32];

        float sbuf[TILE_];
#pragma unroll
        for (int i = 0; i < TILE_; i++) {
            // IIR: exact rounding order of the reference (mul, mul, add, add)
            float y = __fadd_rn(__fadd_rn(__fmul_rn(a1, y1), __fmul_rn(a2, y2)), xt[i]);
            y2 = y1;
            y1 = y;
            float psc = __fadd_rn(y, bo);
            // leak path computed in parallel with the fired-predicate
            float vleak = __fadd_rn(__fmul_rn(dm, v), psc);
            v = fired ? psc : vleak;
            fired = (v > 1.0f);
            sbuf[i] = fired ? 1.0f : 0.0f;
        }

        // vectorized stores, off the critical path
        float4* o4 = (float4*)(orow + t0);
#pragma unroll
        for (int i = 0; i < TILE_ / 4; i++)
            o4[i] = make_float4(sbuf[4*i], sbuf[4*i+1], sbuf[4*i+2], sbuf[4*i+3]);
    }
}

// ---------------------------------------------------------------------------
extern "C" void kernel_launch(void* const* d_in, const int* in_sizes, int n_in,
                              void* d_out, int out_size) {
    (void)in_sizes; (void)n_in; (void)out_size;
    const float* inputs = (const float*)d_in[0];   // [64, 500, 1024]
    const float* a1     = (const float*)d_in[1];   // [500]
    const float* a2     = (const float*)d_in[2];   // [500]
    const float* W      = (const float*)d_in[3];   // [10, 500]
    const float* bias   = (const float*)d_in[4];   // [10]
    float*       out    = (float*)d_out;           // [64, 10, 1024]

    // 128 KB dynamic smem for the stage-in buffer (host-side config; no alloc)
    cudaFuncSetAttribute(iir_lif_kernel,
                         cudaFuncAttributeMaxDynamicSharedMemorySize, SMEM_BYTES);

    dim3 g1(T_ / 128, B_);
    proj_kernel<<<g1, 128>>>(inputs, W);

    iir_lif_kernel<<<CH / 32, 128, SMEM_BYTES>>>(a1, a2, bias, out);
}